// round 10
// baseline (speedup 1.0000x reference)
#include <cuda_runtime.h>
#include <cuda_bf16.h>
#include <cstdint>

// Problem constants
#define M_Q 65536
#define N_K 65536
#define KNB 16
#define CH  64
#define WST 68

// ---------------------------------------------------------------------------
// Device-global scratch
// ---------------------------------------------------------------------------
__device__ float g_A  [CH * CH];
__device__ float g_QG [M_Q * CH];
__device__ float g_KG [N_K * CH];
__device__ float g_RES[M_Q * CH];
__device__ int   g_mask_mode;
// B fragments: [nb(8)][gemm(2)][lane(32)][16 words]
__device__ unsigned int g_BF[8 * 2 * 32 * 16];

#define SWZ128(x) ((x) ^ (((x) >> 3) & 0x70))

// ---------------------------------------------------------------------------
// fp32x2 helpers
// ---------------------------------------------------------------------------
__device__ __forceinline__ unsigned long long fma2(unsigned long long a,
                                                   unsigned long long b,
                                                   unsigned long long c) {
    unsigned long long d;
    asm("fma.rn.f32x2 %0, %1, %2, %3;" : "=l"(d) : "l"(a), "l"(b), "l"(c));
    return d;
}
__device__ __forceinline__ float hsum2(unsigned long long v) {
    float lo, hi;
    asm("mov.b64 {%0, %1}, %2;" : "=f"(lo), "=f"(hi) : "l"(v));
    return lo + hi;
}

// ---------------------------------------------------------------------------
// bf16 split helpers
// ---------------------------------------------------------------------------
__device__ __forceinline__ unsigned int pack_hi(float x0, float x1,
                                                float& r0, float& r1) {
    __nv_bfloat16 b0 = __float2bfloat16(x0), b1 = __float2bfloat16(x1);
    r0 = x0 - __bfloat162float(b0);
    r1 = x1 - __bfloat162float(b1);
    return ((unsigned int)__bfloat16_as_ushort(b1) << 16) |
           (unsigned int)__bfloat16_as_ushort(b0);
}
__device__ __forceinline__ unsigned int pack_lo(float r0, float r1) {
    return ((unsigned int)__bfloat16_as_ushort(__float2bfloat16(r1)) << 16) |
           (unsigned int)__bfloat16_as_ushort(__float2bfloat16(r0));
}

// ---------------------------------------------------------------------------
// mma.sync / ldmatrix wrappers
// ---------------------------------------------------------------------------
__device__ __forceinline__ uint32_t smem_u32(const void* p) {
    uint32_t a;
    asm("{ .reg .u64 t; cvta.to.shared.u64 t, %1; cvt.u32.u64 %0, t; }"
        : "=r"(a) : "l"(p));
    return a;
}
__device__ __forceinline__ void ldsm_x4(uint32_t& a0, uint32_t& a1,
                                        uint32_t& a2, uint32_t& a3, uint32_t addr) {
    asm volatile("ldmatrix.sync.aligned.m8n8.x4.shared.b16 {%0,%1,%2,%3}, [%4];"
                 : "=r"(a0), "=r"(a1), "=r"(a2), "=r"(a3) : "r"(addr));
}
__device__ __forceinline__ void mma16816(float& c0, float& c1, float& c2, float& c3,
                                         uint32_t a0, uint32_t a1, uint32_t a2,
                                         uint32_t a3, uint32_t b0, uint32_t b1) {
    asm volatile(
        "mma.sync.aligned.m16n8k16.row.col.f32.bf16.bf16.f32 "
        "{%0,%1,%2,%3}, {%4,%5,%6,%7}, {%8,%9}, {%0,%1,%2,%3};"
        : "+f"(c0), "+f"(c1), "+f"(c2), "+f"(c3)
        : "r"(a0), "r"(a1), "r"(a2), "r"(a3), "r"(b0), "r"(b1));
}

// ---------------------------------------------------------------------------
// Kernel 1 (fused setup): blocks 0-15 compute A = Wqk@Wg1; blocks 16-47
// build B fragments for Wg2/Wv; block 48 detects mask dtype.
// ---------------------------------------------------------------------------
__global__ void setup_kernel(const float* __restrict__ Wqk,
                             const float* __restrict__ Wg1,
                             const float* __restrict__ Wg2,
                             const float* __restrict__ Wv,
                             const unsigned char* __restrict__ mask) {
    int b = blockIdx.x;
    if (b < 16) {
        int t = b * 256 + threadIdx.x;              // 0..4095
        int r = t >> 6, c = t & 63;
        float s = 0.f;
#pragma unroll
        for (int u = 0; u < CH; u++) s += Wqk[r * CH + u] * Wg1[u * CH + c];
        g_A[t] = s;
    } else if (b < 48) {
        int idx = (b - 16) * 256 + threadIdx.x;     // 0..8191
        int nb   = idx >> 10;
        int rem  = idx & 1023;
        int gm   = rem >> 9;
        int rem2 = rem & 511;
        int lane = rem2 >> 4;
        int w    = rem2 & 15;
        int split = w >> 3, kb = (w >> 1) & 3, r = w & 1;
        int t2 = lane & 3, gg = lane >> 2;
        int k0 = kb * 16 + 2 * t2 + (r ? 8 : 0);
        int n  = nb * 8 + gg;
        const float* W = gm ? Wv : Wg2;
        float w0 = W[k0 * CH + n];
        float w1 = W[(k0 + 1) * CH + n];
        unsigned int word;
        if (split == 0) { float r0, r1; word = pack_hi(w0, w1, r0, r1); }
        else {
            __nv_bfloat16 b0 = __float2bfloat16(w0), b1 = __float2bfloat16(w1);
            word = pack_lo(w0 - __bfloat162float(b0), w1 - __bfloat162float(b1));
        }
        g_BF[idx] = word;
    } else {
        __shared__ int sA, sB;
        int tid = threadIdx.x;
        if (tid == 0) { sA = 0; sB = 0; }
        __syncthreads();
        const uint4* p = (const uint4*)mask;
        int nvec = (M_Q * KNB) / 16;
        int fA = 0, fB = 0;
        for (int i = tid; i < nvec; i += blockDim.x) {
            uint4 v = p[i];
            unsigned w[4] = {v.x, v.y, v.z, v.w};
#pragma unroll
            for (int j = 0; j < 4; j++) {
                if ((w[j] >> 24) == 0x3fu) fA = 1;
                if (w[j] & 0x00ffff00u)    fB = 1;
                if ((w[j] >> 24) && ((w[j] >> 24) != 0x3fu)) fB = 1;
            }
        }
        if (fA) atomicOr(&sA, 1);
        if (fB) atomicOr(&sB, 1);
        __syncthreads();
        if (tid == 0) g_mask_mode = sA ? 2 : (sB ? 0 : 1);
    }
}

// ---------------------------------------------------------------------------
// Dummy no-op kernel (positions attn as the profiled 4th launch)
// ---------------------------------------------------------------------------
__global__ void dummy_kernel() {}

// ---------------------------------------------------------------------------
// Kernel 2: merged projection (fma2 path, unchanged)
// ---------------------------------------------------------------------------
__global__ __launch_bounds__(256) void project_kernel(
    const float* __restrict__ q, const float* __restrict__ q_pos,
    const float* __restrict__ k, const float* __restrict__ k_pos,
    const float* __restrict__ bg1)
{
    __shared__ __align__(16) float AT[CH * WST];
    __shared__ __align__(16) float rowbuf[8][8 * CH];
    __shared__ float bsh[CH];

    int tid = threadIdx.x, lane = tid & 31, wid = tid >> 5;

    for (int i = tid; i < CH * CH; i += 256) {
        int t = i >> 6, c = i & 63;
        AT[c * WST + t] = g_A[i];
    }
    if (tid < CH) bsh[tid] = bg1[tid];
    __syncthreads();

    int row0 = blockIdx.x * 64 + wid * 8;
    bool is_q = row0 < M_Q;
    const float* src = is_q ? q : k;
    const float* pos = is_q ? q_pos : k_pos;
    float* dst       = is_q ? g_QG : g_KG;
    int r0 = is_q ? row0 : row0 - M_Q;

    float* rb = &rowbuf[wid][0];
#pragma unroll
    for (int j = 0; j < 8; j++) {
        const float2* s2 = (const float2*)(src + (size_t)(r0 + j) * CH);
        const float2* p2 = (const float2*)(pos + (size_t)(r0 + j) * CH);
        float2 a = s2[lane], b = p2[lane];
        ((float2*)(rb + j * CH))[lane] = make_float2(a.x + b.x, a.y + b.y);
    }
    __syncwarp();

    unsigned long long accA[8], accB[8];
#pragma unroll
    for (int j = 0; j < 8; j++) { accA[j] = 0ull; accB[j] = 0ull; }
    const float* wr0 = AT + lane * WST;
    const float* wr1 = AT + (lane + 32) * WST;

#pragma unroll
    for (int t4 = 0; t4 < CH; t4 += 4) {
        ulonglong2 wa = *reinterpret_cast<const ulonglong2*>(wr0 + t4);
        ulonglong2 wb = *reinterpret_cast<const ulonglong2*>(wr1 + t4);
#pragma unroll
        for (int j = 0; j < 8; j++) {
            ulonglong2 hp = *reinterpret_cast<const ulonglong2*>(rb + j * CH + t4);
            accA[j] = fma2(hp.x, wa.x, accA[j]);
            accA[j] = fma2(hp.y, wa.y, accA[j]);
            accB[j] = fma2(hp.x, wb.x, accB[j]);
            accB[j] = fma2(hp.y, wb.y, accB[j]);
        }
    }
    float b0 = is_q ? bsh[lane] : 0.f;
    float b1 = is_q ? bsh[lane + 32] : 0.f;
#pragma unroll
    for (int j = 0; j < 8; j++) {
        dst[(size_t)(r0 + j) * CH + lane]      = hsum2(accA[j]) + b0;
        dst[(size_t)(r0 + j) * CH + 32 + lane] = hsum2(accB[j]) + b1;
    }
}

// ---------------------------------------------------------------------------
// Kernel 3: HMMA attention, per-m-block fused pipeline.
//   Warp = (mg of 2 m-blocks, ng of 4 n-blocks). For each owned m-block:
//   GEMM1 (logits, regs) -> GEMM2 (vproj) -> fused softmax epilogue.
//   No D1 smem buffer, no max-subtraction (logits bounded; masked p=0).
// smem: h_hi 16K | h_lo 16K | v_hi 16K | v_lo 16K | mask 512  = 66048 B
// ---------------------------------------------------------------------------
#define SM_HH 0
#define SM_HL 16384
#define SM_VH 32768
#define SM_VL 49152
#define SM_MK 65536
#define ATT_SMEM 66048

__global__ __launch_bounds__(256, 2) void attn_mma_kernel(
    const float* __restrict__ value, const unsigned char* __restrict__ mask,
    const int* __restrict__ knn, const float* __restrict__ bv)
{
    extern __shared__ __align__(1024) char smc[];
    int* smask = (int*)(smc + SM_MK);

    int tid = threadIdx.x, lane = tid & 31, wid = tid >> 5;
    int m0 = blockIdx.x * 8;
    int t = lane & 3, gg = lane >> 2;

    uint32_t sb_hh = smem_u32(smc + SM_HH);
    uint32_t sb_hl = smem_u32(smc + SM_HL);
    uint32_t sb_vh = smem_u32(smc + SM_VH);
    uint32_t sb_vl = smem_u32(smc + SM_VL);

    // ---- mask preload ----
    if (tid < 128) {
        int qloc = tid >> 4, e = tid & 15;
        size_t ix = (size_t)(m0 + qloc) * KNB + e;
        int mmode = g_mask_mode, mk;
        if (mmode == 0)      mk = mask[ix] != 0;
        else if (mmode == 1) mk = ((const int*)mask)[ix] != 0;
        else                 mk = ((const float*)mask)[ix] != 0.f;
        smask[tid] = mk;
    }

    // ---- build h AND value tiles upfront (warp w = query w) ----
    int mq = m0 + wid;
    int nbr = 0;
    if (lane < KNB) nbr = knn[(size_t)M_Q * KNB + (size_t)mq * KNB + lane];
    float2 qg = ((const float2*)(g_QG + (size_t)mq * CH))[lane];

#pragma unroll
    for (int e = 0; e < KNB; e++) {
        int n = __shfl_sync(0xffffffffu, nbr, e);
        float2 kg = ((const float2*)(g_KG + (size_t)n * CH))[lane];
        float x0 = fmaxf(qg.x - kg.x, 0.f), x1 = fmaxf(qg.y - kg.y, 0.f);
        unsigned off = SWZ128((unsigned)((wid * KNB + e) * 128 + lane * 4));
        float r0, r1;
        unsigned hiw = pack_hi(x0, x1, r0, r1);
        *(unsigned*)(smc + SM_HH + off) = hiw;
        *(unsigned*)(smc + SM_HL + off) = pack_lo(r0, r1);
    }
#pragma unroll
    for (int e = 0; e < KNB; e++) {
        float2 v2 = ((const float2*)(value + ((size_t)mq * KNB + e) * CH))[lane];
        unsigned off = SWZ128((unsigned)((wid * KNB + e) * 128 + lane * 4));
        float r0, r1;
        unsigned hiw = pack_hi(v2.x, v2.y, r0, r1);
        *(unsigned*)(smc + SM_VH + off) = hiw;
        *(unsigned*)(smc + SM_VL + off) = pack_lo(r0, r1);
    }
    __syncthreads();

    int mg = wid >> 1;       // m-blocks {2mg, 2mg+1}
    int ng = wid & 1;        // n-blocks [4ng, 4ng+4)

    unsigned lmrow = (unsigned)(lane & 15);
    unsigned lmcol = (unsigned)((lane >> 4) & 1) * 16;

    float2 bvv[4];
#pragma unroll
    for (int nb = 0; nb < 4; nb++)
        bvv[nb] = *(const float2*)(bv + (ng * 4 + nb) * 8 + 2 * t);

#pragma unroll
    for (int mbi = 0; mbi < 2; mbi++) {
        int b = mg * 2 + mbi;
        unsigned rowoff = (unsigned)(b * 16 + lmrow) * 128 + lmcol;

        // ---- GEMM1: logits in regs ----
        uint32_t BH[4][8], BL[4][8];
#pragma unroll
        for (int nb = 0; nb < 4; nb++) {
            const uint4* bp = (const uint4*)g_BF +
                ((size_t)((ng * 4 + nb) * 2 + 0) * 32 + lane) * 4;
            uint4 q0 = bp[0], q1 = bp[1], q2 = bp[2], q3 = bp[3];
            BH[nb][0]=q0.x; BH[nb][1]=q0.y; BH[nb][2]=q0.z; BH[nb][3]=q0.w;
            BH[nb][4]=q1.x; BH[nb][5]=q1.y; BH[nb][6]=q1.z; BH[nb][7]=q1.w;
            BL[nb][0]=q2.x; BL[nb][1]=q2.y; BL[nb][2]=q2.z; BL[nb][3]=q2.w;
            BL[nb][4]=q3.x; BL[nb][5]=q3.y; BL[nb][6]=q3.z; BL[nb][7]=q3.w;
        }
        float c1[4][4];
#pragma unroll
        for (int nb = 0; nb < 4; nb++)
#pragma unroll
            for (int j = 0; j < 4; j++) c1[nb][j] = 0.f;
#pragma unroll
        for (int kb = 0; kb < 4; kb++) {
            unsigned off = SWZ128(rowoff + kb * 32);
            uint32_t a0, a1, a2, a3, l0, l1, l2, l3;
            ldsm_x4(a0, a1, a2, a3, sb_hh + off);
            ldsm_x4(l0, l1, l2, l3, sb_hl + off);
#pragma unroll
            for (int nb = 0; nb < 4; nb++) {
                mma16816(c1[nb][0], c1[nb][1], c1[nb][2], c1[nb][3],
                         a0, a1, a2, a3, BH[nb][kb*2], BH[nb][kb*2+1]);
                mma16816(c1[nb][0], c1[nb][1], c1[nb][2], c1[nb][3],
                         a0, a1, a2, a3, BL[nb][kb*2], BL[nb][kb*2+1]);
                mma16816(c1[nb][0], c1[nb][1], c1[nb][2], c1[nb][3],
                         l0, l1, l2, l3, BH[nb][kb*2], BH[nb][kb*2+1]);
            }
        }

        // ---- GEMM2: vproj (B frags overwritten) ----
#pragma unroll
        for (int nb = 0; nb < 4; nb++) {
            const uint4* bp = (const uint4*)g_BF +
                ((size_t)((ng * 4 + nb) * 2 + 1) * 32 + lane) * 4;
            uint4 q0 = bp[0], q1 = bp[1], q2 = bp[2], q3 = bp[3];
            BH[nb][0]=q0.x; BH[nb][1]=q0.y; BH[nb][2]=q0.z; BH[nb][3]=q0.w;
            BH[nb][4]=q1.x; BH[nb][5]=q1.y; BH[nb][6]=q1.z; BH[nb][7]=q1.w;
            BL[nb][0]=q2.x; BL[nb][1]=q2.y; BL[nb][2]=q2.z; BL[nb][3]=q2.w;
            BL[nb][4]=q3.x; BL[nb][5]=q3.y; BL[nb][6]=q3.z; BL[nb][7]=q3.w;
        }
        float c2[4][4];
#pragma unroll
        for (int nb = 0; nb < 4; nb++)
#pragma unroll
            for (int j = 0; j < 4; j++) c2[nb][j] = 0.f;
#pragma unroll
        for (int kb = 0; kb < 4; kb++) {
            unsigned off = SWZ128(rowoff + kb * 32);
            uint32_t a0, a1, a2, a3, l0, l1, l2, l3;
            ldsm_x4(a0, a1, a2, a3, sb_vh + off);
            ldsm_x4(l0, l1, l2, l3, sb_vl + off);
#pragma unroll
            for (int nb = 0; nb < 4; nb++) {
                mma16816(c2[nb][0], c2[nb][1], c2[nb][2], c2[nb][3],
                         a0, a1, a2, a3, BH[nb][kb*2], BH[nb][kb*2+1]);
                mma16816(c2[nb][0], c2[nb][1], c2[nb][2], c2[nb][3],
                         a0, a1, a2, a3, BL[nb][kb*2], BL[nb][kb*2+1]);
                mma16816(c2[nb][0], c2[nb][1], c2[nb][2], c2[nb][3],
                         l0, l1, l2, l3, BH[nb][kb*2], BH[nb][kb*2+1]);
            }
        }

        // ---- fused epilogue (no max-sub; masked p = 0) ----
        int mka = smask[b * 16 + gg];
        int mkb = smask[b * 16 + gg + 8];
#pragma unroll
        for (int nb = 0; nb < 4; nb++) {
            float p0 = mka ? 0.f : __expf(c1[nb][0]);
            float p1 = mka ? 0.f : __expf(c1[nb][1]);
            float p2 = mkb ? 0.f : __expf(c1[nb][2]);
            float p3 = mkb ? 0.f : __expf(c1[nb][3]);
            float s0 = p0 + p2, s1 = p1 + p3;
            float w0 = p0 * c2[nb][0] + p2 * c2[nb][2];
            float w1 = p1 * c2[nb][1] + p3 * c2[nb][3];
#pragma unroll
            for (int s = 4; s < 32; s <<= 1) {
                s0 += __shfl_xor_sync(0xffffffffu, s0, s);
                s1 += __shfl_xor_sync(0xffffffffu, s1, s);
                w0 += __shfl_xor_sync(0xffffffffu, w0, s);
                w1 += __shfl_xor_sync(0xffffffffu, w1, s);
            }
            if (lane < 4) {
                float2 o = make_float2(w0 / s0 + bvv[nb].x, w1 / s1 + bvv[nb].y);
                *(float2*)(g_RES + (size_t)(m0 + b) * CH + (ng * 4 + nb) * 8 + 2 * t) = o;
            }
        }
    }
}

// ---------------------------------------------------------------------------
// Kernel 4: out = g_RES @ Wt + bt
// ---------------------------------------------------------------------------
__global__ __launch_bounds__(256) void outproj_kernel(
    const float* __restrict__ Wt, const float* __restrict__ bt,
    float* __restrict__ out)
{
    __shared__ __align__(16) float WT[CH * WST];
    __shared__ __align__(16) float rowbuf[8][8 * CH];
    __shared__ float bsh[CH];

    int tid = threadIdx.x, lane = tid & 31, wid = tid >> 5;

    for (int i = tid; i < CH * CH; i += 256) {
        int t = i >> 6, c = i & 63;
        WT[c * WST + t] = Wt[i];
    }
    if (tid < CH) bsh[tid] = bt[tid];
    __syncthreads();

    int r0 = blockIdx.x * 64 + wid * 8;
    float* rb = &rowbuf[wid][0];
#pragma unroll
    for (int j = 0; j < 8; j++) {
        ((float2*)(rb + j * CH))[lane] =
            ((const float2*)(g_RES + (size_t)(r0 + j) * CH))[lane];
    }
    __syncwarp();

    unsigned long long accA[8], accB[8];
#pragma unroll
    for (int j = 0; j < 8; j++) { accA[j] = 0ull; accB[j] = 0ull; }
    const float* wr0 = WT + lane * WST;
    const float* wr1 = WT + (lane + 32) * WST;

#pragma unroll
    for (int t4 = 0; t4 < CH; t4 += 4) {
        ulonglong2 wa = *reinterpret_cast<const ulonglong2*>(wr0 + t4);
        ulonglong2 wb = *reinterpret_cast<const ulonglong2*>(wr1 + t4);
#pragma unroll
        for (int j = 0; j < 8; j++) {
            ulonglong2 hp = *reinterpret_cast<const ulonglong2*>(rb + j * CH + t4);
            accA[j] = fma2(hp.x, wa.x, accA[j]);
            accA[j] = fma2(hp.y, wa.y, accA[j]);
            accB[j] = fma2(hp.x, wb.x, accB[j]);
            accB[j] = fma2(hp.y, wb.y, accB[j]);
        }
    }
#pragma unroll
    for (int j = 0; j < 8; j++) {
        out[(size_t)(r0 + j) * CH + lane]      = hsum2(accA[j]) + bsh[lane];
        out[(size_t)(r0 + j) * CH + 32 + lane] = hsum2(accB[j]) + bsh[lane + 32];
    }
}

// ---------------------------------------------------------------------------
// kernel_launch   (attn is my 4th launch -> captured by ncu -s 5 -c 1)
// ---------------------------------------------------------------------------
extern "C" void kernel_launch(void* const* d_in, const int* in_sizes, int n_in,
                              void* d_out, int out_size)
{
    const float* q      = (const float*)d_in[0];
    const float* k      = (const float*)d_in[1];
    const float* value  = (const float*)d_in[2];
    const float* q_pos  = (const float*)d_in[3];
    const float* k_pos  = (const float*)d_in[4];
    const unsigned char* mask = (const unsigned char*)d_in[5];
    const int*   knn    = (const int*)d_in[6];
    const float* Wqk    = (const float*)d_in[8];
    const float* Wv     = (const float*)d_in[10];
    const float* bv     = (const float*)d_in[11];
    const float* Wg1    = (const float*)d_in[12];
    const float* bg1    = (const float*)d_in[13];
    const float* Wg2    = (const float*)d_in[14];
    const float* Wt     = (const float*)d_in[16];
    const float* bt     = (const float*)d_in[17];
    float* out = (float*)d_out;

    cudaFuncSetAttribute(attn_mma_kernel,
                         cudaFuncAttributeMaxDynamicSharedMemorySize, ATT_SMEM);

    setup_kernel<<<49, 256>>>(Wqk, Wg1, Wg2, Wv, mask);
    project_kernel<<<(M_Q + N_K) / 64, 256>>>(q, q_pos, k, k_pos, bg1);
    dummy_kernel<<<1, 1>>>();
    attn_mma_kernel<<<M_Q / 8, 256, ATT_SMEM>>>(value, mask, knn, bv);
    outproj_kernel<<<M_Q / 64, 256>>>(Wt, bt, out);
}

// round 13
// speedup vs baseline: 1.0073x; 1.0073x over previous
#include <cuda_runtime.h>
#include <cuda_bf16.h>
#include <cstdint>

// Problem constants
#define M_Q 65536
#define N_K 65536
#define KNB 16
#define CH  64
#define WST 68

// ---------------------------------------------------------------------------
// Device-global scratch
// ---------------------------------------------------------------------------
__device__ float g_A  [CH * CH];
__device__ float g_QG [M_Q * CH];
__device__ float g_KG [N_K * CH];
__device__ float g_RES[M_Q * CH];
__device__ int   g_mask_mode;
// B fragments: [nb(8)][gemm(2)][lane(32)][16 words]
__device__ unsigned int g_BF[8 * 2 * 32 * 16];

// ---------------------------------------------------------------------------
// fp32x2 helpers (projection kernels)
// ---------------------------------------------------------------------------
__device__ __forceinline__ unsigned long long fma2(unsigned long long a,
                                                   unsigned long long b,
                                                   unsigned long long c) {
    unsigned long long d;
    asm("fma.rn.f32x2 %0, %1, %2, %3;" : "=l"(d) : "l"(a), "l"(b), "l"(c));
    return d;
}
__device__ __forceinline__ float hsum2(unsigned long long v) {
    float lo, hi;
    asm("mov.b64 {%0, %1}, %2;" : "=f"(lo), "=f"(hi) : "l"(v));
    return lo + hi;
}

// ---------------------------------------------------------------------------
// bf16 split helpers
// ---------------------------------------------------------------------------
__device__ __forceinline__ unsigned int pack_hi(float x0, float x1,
                                                float& r0, float& r1) {
    __nv_bfloat16 b0 = __float2bfloat16(x0), b1 = __float2bfloat16(x1);
    r0 = x0 - __bfloat162float(b0);
    r1 = x1 - __bfloat162float(b1);
    return ((unsigned int)__bfloat16_as_ushort(b1) << 16) |
           (unsigned int)__bfloat16_as_ushort(b0);
}
__device__ __forceinline__ unsigned int pack_lo(float r0, float r1) {
    return ((unsigned int)__bfloat16_as_ushort(__float2bfloat16(r1)) << 16) |
           (unsigned int)__bfloat16_as_ushort(__float2bfloat16(r0));
}

// ---------------------------------------------------------------------------
// mma.sync wrapper
// ---------------------------------------------------------------------------
__device__ __forceinline__ void mma16816(float& c0, float& c1, float& c2, float& c3,
                                         uint32_t a0, uint32_t a1, uint32_t a2,
                                         uint32_t a3, uint32_t b0, uint32_t b1) {
    asm volatile(
        "mma.sync.aligned.m16n8k16.row.col.f32.bf16.bf16.f32 "
        "{%0,%1,%2,%3}, {%4,%5,%6,%7}, {%8,%9}, {%0,%1,%2,%3};"
        : "+f"(c0), "+f"(c1), "+f"(c2), "+f"(c3)
        : "r"(a0), "r"(a1), "r"(a2), "r"(a3), "r"(b0), "r"(b1));
}

__device__ __forceinline__ int load_mask(const unsigned char* mask, size_t ix,
                                         int mode) {
    if (mode == 0) return mask[ix] != 0;
    if (mode == 1) return ((const int*)mask)[ix] != 0;
    return ((const float*)mask)[ix] != 0.f;
}

// ---------------------------------------------------------------------------
// Kernel 1 (fused setup): blocks 0-15 A = Wqk@Wg1; 16-47 B fragments;
// block 48 mask dtype detection.
// ---------------------------------------------------------------------------
__global__ void setup_kernel(const float* __restrict__ Wqk,
                             const float* __restrict__ Wg1,
                             const float* __restrict__ Wg2,
                             const float* __restrict__ Wv,
                             const unsigned char* __restrict__ mask) {
    int b = blockIdx.x;
    if (b < 16) {
        int t = b * 256 + threadIdx.x;
        int r = t >> 6, c = t & 63;
        float s = 0.f;
#pragma unroll
        for (int u = 0; u < CH; u++) s += Wqk[r * CH + u] * Wg1[u * CH + c];
        g_A[t] = s;
    } else if (b < 48) {
        int idx = (b - 16) * 256 + threadIdx.x;
        int nb   = idx >> 10;
        int rem  = idx & 1023;
        int gm   = rem >> 9;
        int rem2 = rem & 511;
        int lane = rem2 >> 4;
        int w    = rem2 & 15;
        int split = w >> 3, kb = (w >> 1) & 3, r = w & 1;
        int t2 = lane & 3, gg = lane >> 2;
        int k0 = kb * 16 + 2 * t2 + (r ? 8 : 0);
        int n  = nb * 8 + gg;
        const float* W = gm ? Wv : Wg2;
        float w0 = W[k0 * CH + n];
        float w1 = W[(k0 + 1) * CH + n];
        unsigned int word;
        if (split == 0) { float r0, r1; word = pack_hi(w0, w1, r0, r1); }
        else {
            __nv_bfloat16 b0 = __float2bfloat16(w0), b1 = __float2bfloat16(w1);
            word = pack_lo(w0 - __bfloat162float(b0), w1 - __bfloat162float(b1));
        }
        g_BF[idx] = word;
    } else {
        __shared__ int sA, sB;
        int tid = threadIdx.x;
        if (tid == 0) { sA = 0; sB = 0; }
        __syncthreads();
        const uint4* p = (const uint4*)mask;
        int nvec = (M_Q * KNB) / 16;
        int fA = 0, fB = 0;
        for (int i = tid; i < nvec; i += blockDim.x) {
            uint4 v = p[i];
            unsigned w[4] = {v.x, v.y, v.z, v.w};
#pragma unroll
            for (int j = 0; j < 4; j++) {
                if ((w[j] >> 24) == 0x3fu) fA = 1;
                if (w[j] & 0x00ffff00u)    fB = 1;
                if ((w[j] >> 24) && ((w[j] >> 24) != 0x3fu)) fB = 1;
            }
        }
        if (fA) atomicOr(&sA, 1);
        if (fB) atomicOr(&sB, 1);
        __syncthreads();
        if (tid == 0) g_mask_mode = sA ? 2 : (sB ? 0 : 1);
    }
}

// ---------------------------------------------------------------------------
// Dummy no-op kernel (positions attn as the profiled 4th launch)
// ---------------------------------------------------------------------------
__global__ void dummy_kernel() {}

// ---------------------------------------------------------------------------
// Kernel 2: merged projection (fma2 path, unchanged)
// ---------------------------------------------------------------------------
__global__ __launch_bounds__(256) void project_kernel(
    const float* __restrict__ q, const float* __restrict__ q_pos,
    const float* __restrict__ k, const float* __restrict__ k_pos,
    const float* __restrict__ bg1)
{
    __shared__ __align__(16) float AT[CH * WST];
    __shared__ __align__(16) float rowbuf[8][8 * CH];
    __shared__ float bsh[CH];

    int tid = threadIdx.x, lane = tid & 31, wid = tid >> 5;

    for (int i = tid; i < CH * CH; i += 256) {
        int t = i >> 6, c = i & 63;
        AT[c * WST + t] = g_A[i];
    }
    if (tid < CH) bsh[tid] = bg1[tid];
    __syncthreads();

    int row0 = blockIdx.x * 64 + wid * 8;
    bool is_q = row0 < M_Q;
    const float* src = is_q ? q : k;
    const float* pos = is_q ? q_pos : k_pos;
    float* dst       = is_q ? g_QG : g_KG;
    int r0 = is_q ? row0 : row0 - M_Q;

    float* rb = &rowbuf[wid][0];
#pragma unroll
    for (int j = 0; j < 8; j++) {
        const float2* s2 = (const float2*)(src + (size_t)(r0 + j) * CH);
        const float2* p2 = (const float2*)(pos + (size_t)(r0 + j) * CH);
        float2 a = s2[lane], b = p2[lane];
        ((float2*)(rb + j * CH))[lane] = make_float2(a.x + b.x, a.y + b.y);
    }
    __syncwarp();

    unsigned long long accA[8], accB[8];
#pragma unroll
    for (int j = 0; j < 8; j++) { accA[j] = 0ull; accB[j] = 0ull; }
    const float* wr0 = AT + lane * WST;
    const float* wr1 = AT + (lane + 32) * WST;

#pragma unroll
    for (int t4 = 0; t4 < CH; t4 += 4) {
        ulonglong2 wa = *reinterpret_cast<const ulonglong2*>(wr0 + t4);
        ulonglong2 wb = *reinterpret_cast<const ulonglong2*>(wr1 + t4);
#pragma unroll
        for (int j = 0; j < 8; j++) {
            ulonglong2 hp = *reinterpret_cast<const ulonglong2*>(rb + j * CH + t4);
            accA[j] = fma2(hp.x, wa.x, accA[j]);
            accA[j] = fma2(hp.y, wa.y, accA[j]);
            accB[j] = fma2(hp.x, wb.x, accB[j]);
            accB[j] = fma2(hp.y, wb.y, accB[j]);
        }
    }
    float b0 = is_q ? bsh[lane] : 0.f;
    float b1 = is_q ? bsh[lane + 32] : 0.f;
#pragma unroll
    for (int j = 0; j < 8; j++) {
        dst[(size_t)(r0 + j) * CH + lane]      = hsum2(accA[j]) + b0;
        dst[(size_t)(r0 + j) * CH + 32 + lane] = hsum2(accB[j]) + b1;
    }
}

// ---------------------------------------------------------------------------
// Kernel 3: HMMA attention with DIRECT global->register fragments.
//   No smem, no syncthreads, no ldmatrix. Block = 128 thr = 4 queries.
//   Warp = (mg: 2 queries, ng: 4 n-blocks). m16n8k16 A-frag per lane
//   (g=lane>>2, t=lane&3): rows {g, g+8}, col-pairs {2t, 2t+8} per k-block.
// ---------------------------------------------------------------------------
__global__ __launch_bounds__(128, 4) void attn_direct_kernel(
    const float* __restrict__ value, const unsigned char* __restrict__ mask,
    const int* __restrict__ knn, const float* __restrict__ bv)
{
    int tid = threadIdx.x, lane = tid & 31, wid = tid >> 5;
    int q0 = blockIdx.x * 4;
    int mg = wid >> 1, ng = wid & 1;
    int g = lane >> 2, t = lane & 3;
    int mmode = g_mask_mode;

    float2 bvv[4];
#pragma unroll
    for (int nb = 0; nb < 4; nb++)
        bvv[nb] = *(const float2*)(bv + (ng * 4 + nb) * 8 + 2 * t);

    uint32_t BH[4][8], BL[4][8];

#pragma unroll
    for (int mbi = 0; mbi < 2; mbi++) {
        int q = q0 + mg * 2 + mbi;
        int e1 = g, e2 = g + 8;
        size_t eix1 = (size_t)q * KNB + e1;
        size_t eix2 = (size_t)q * KNB + e2;
        int i1 = knn[(size_t)M_Q * KNB + eix1];
        int i2 = knn[(size_t)M_Q * KNB + eix2];
        int mk1 = load_mask(mask, eix1, mmode);
        int mk2 = load_mask(mask, eix2, mmode);
        const float* qrow  = g_QG + (size_t)q * CH;
        const float* krow1 = g_KG + (size_t)i1 * CH;
        const float* krow2 = g_KG + (size_t)i2 * CH;
        const float* vrow1 = value + ((size_t)q * KNB + e1) * CH;
        const float* vrow2 = value + ((size_t)q * KNB + e2) * CH;

        // ---- B fragments for GEMM1 (Wg2) ----
#pragma unroll
        for (int nb = 0; nb < 4; nb++) {
            const uint4* bp = (const uint4*)g_BF +
                ((size_t)((ng * 4 + nb) * 2 + 0) * 32 + lane) * 4;
            uint4 u0 = bp[0], u1 = bp[1], u2 = bp[2], u3 = bp[3];
            BH[nb][0]=u0.x; BH[nb][1]=u0.y; BH[nb][2]=u0.z; BH[nb][3]=u0.w;
            BH[nb][4]=u1.x; BH[nb][5]=u1.y; BH[nb][6]=u1.z; BH[nb][7]=u1.w;
            BL[nb][0]=u2.x; BL[nb][1]=u2.y; BL[nb][2]=u2.z; BL[nb][3]=u2.w;
            BL[nb][4]=u3.x; BL[nb][5]=u3.y; BL[nb][6]=u3.z; BL[nb][7]=u3.w;
        }

        // ---- GEMM1: logits = relu(QG[q] - KG[idx]) @ Wg2 (3-term split) ----
        float c1[4][4];
#pragma unroll
        for (int nb = 0; nb < 4; nb++)
#pragma unroll
            for (int j = 0; j < 4; j++) c1[nb][j] = 0.f;
#pragma unroll
        for (int kb = 0; kb < 4; kb++) {
            int c = kb * 16 + 2 * t;
            float2 qa = *(const float2*)(qrow + c);
            float2 qb = *(const float2*)(qrow + c + 8);
            float2 ka = *(const float2*)(krow1 + c);
            float2 kc = *(const float2*)(krow2 + c);
            float2 kbp = *(const float2*)(krow1 + c + 8);
            float2 kd = *(const float2*)(krow2 + c + 8);
            float x00 = fmaxf(qa.x - ka.x, 0.f),  x01 = fmaxf(qa.y - ka.y, 0.f);
            float x10 = fmaxf(qa.x - kc.x, 0.f),  x11 = fmaxf(qa.y - kc.y, 0.f);
            float x20 = fmaxf(qb.x - kbp.x, 0.f), x21 = fmaxf(qb.y - kbp.y, 0.f);
            float x30 = fmaxf(qb.x - kd.x, 0.f),  x31 = fmaxf(qb.y - kd.y, 0.f);
            float r00, r01, r10, r11, r20, r21, r30, r31;
            uint32_t ah0 = pack_hi(x00, x01, r00, r01);
            uint32_t ah1 = pack_hi(x10, x11, r10, r11);
            uint32_t ah2 = pack_hi(x20, x21, r20, r21);
            uint32_t ah3 = pack_hi(x30, x31, r30, r31);
            uint32_t al0 = pack_lo(r00, r01);
            uint32_t al1 = pack_lo(r10, r11);
            uint32_t al2 = pack_lo(r20, r21);
            uint32_t al3 = pack_lo(r30, r31);
#pragma unroll
            for (int nb = 0; nb < 4; nb++) {
                mma16816(c1[nb][0], c1[nb][1], c1[nb][2], c1[nb][3],
                         ah0, ah1, ah2, ah3, BH[nb][kb*2], BH[nb][kb*2+1]);
                mma16816(c1[nb][0], c1[nb][1], c1[nb][2], c1[nb][3],
                         ah0, ah1, ah2, ah3, BL[nb][kb*2], BL[nb][kb*2+1]);
                mma16816(c1[nb][0], c1[nb][1], c1[nb][2], c1[nb][3],
                         al0, al1, al2, al3, BH[nb][kb*2], BH[nb][kb*2+1]);
            }
        }

        // ---- B fragments for GEMM2 (Wv) ----
#pragma unroll
        for (int nb = 0; nb < 4; nb++) {
            const uint4* bp = (const uint4*)g_BF +
                ((size_t)((ng * 4 + nb) * 2 + 1) * 32 + lane) * 4;
            uint4 u0 = bp[0], u1 = bp[1], u2 = bp[2], u3 = bp[3];
            BH[nb][0]=u0.x; BH[nb][1]=u0.y; BH[nb][2]=u0.z; BH[nb][3]=u0.w;
            BH[nb][4]=u1.x; BH[nb][5]=u1.y; BH[nb][6]=u1.z; BH[nb][7]=u1.w;
            BL[nb][0]=u2.x; BL[nb][1]=u2.y; BL[nb][2]=u2.z; BL[nb][3]=u2.w;
            BL[nb][4]=u3.x; BL[nb][5]=u3.y; BL[nb][6]=u3.z; BL[nb][7]=u3.w;
        }

        // ---- GEMM2: vproj = value @ Wv ----
        float c2[4][4];
#pragma unroll
        for (int nb = 0; nb < 4; nb++)
#pragma unroll
            for (int j = 0; j < 4; j++) c2[nb][j] = 0.f;
#pragma unroll
        for (int kb = 0; kb < 4; kb++) {
            int c = kb * 16 + 2 * t;
            float2 va = *(const float2*)(vrow1 + c);
            float2 wa = *(const float2*)(vrow2 + c);
            float2 vb = *(const float2*)(vrow1 + c + 8);
            float2 wb = *(const float2*)(vrow2 + c + 8);
            float r00, r01, r10, r11, r20, r21, r30, r31;
            uint32_t ah0 = pack_hi(va.x, va.y, r00, r01);
            uint32_t ah1 = pack_hi(wa.x, wa.y, r10, r11);
            uint32_t ah2 = pack_hi(vb.x, vb.y, r20, r21);
            uint32_t ah3 = pack_hi(wb.x, wb.y, r30, r31);
            uint32_t al0 = pack_lo(r00, r01);
            uint32_t al1 = pack_lo(r10, r11);
            uint32_t al2 = pack_lo(r20, r21);
            uint32_t al3 = pack_lo(r30, r31);
#pragma unroll
            for (int nb = 0; nb < 4; nb++) {
                mma16816(c2[nb][0], c2[nb][1], c2[nb][2], c2[nb][3],
                         ah0, ah1, ah2, ah3, BH[nb][kb*2], BH[nb][kb*2+1]);
                mma16816(c2[nb][0], c2[nb][1], c2[nb][2], c2[nb][3],
                         ah0, ah1, ah2, ah3, BL[nb][kb*2], BL[nb][kb*2+1]);
                mma16816(c2[nb][0], c2[nb][1], c2[nb][2], c2[nb][3],
                         al0, al1, al2, al3, BH[nb][kb*2], BH[nb][kb*2+1]);
            }
        }

        // ---- fused softmax epilogue (no max-sub; masked p = 0) ----
#pragma unroll
        for (int nb = 0; nb < 4; nb++) {
            float p0 = mk1 ? 0.f : __expf(c1[nb][0]);
            float p1 = mk1 ? 0.f : __expf(c1[nb][1]);
            float p2 = mk2 ? 0.f : __expf(c1[nb][2]);
            float p3 = mk2 ? 0.f : __expf(c1[nb][3]);
            float s0 = p0 + p2, s1 = p1 + p3;
            float w0 = p0 * c2[nb][0] + p2 * c2[nb][2];
            float w1 = p1 * c2[nb][1] + p3 * c2[nb][3];
#pragma unroll
            for (int s = 4; s < 32; s <<= 1) {
                s0 += __shfl_xor_sync(0xffffffffu, s0, s);
                s1 += __shfl_xor_sync(0xffffffffu, s1, s);
                w0 += __shfl_xor_sync(0xffffffffu, w0, s);
                w1 += __shfl_xor_sync(0xffffffffu, w1, s);
            }
            if (lane < 4) {
                float2 o = make_float2(w0 / s0 + bvv[nb].x, w1 / s1 + bvv[nb].y);
                *(float2*)(g_RES + (size_t)q * CH + (ng * 4 + nb) * 8 + 2 * t) = o;
            }
        }
    }
}

// ---------------------------------------------------------------------------
// Kernel 4: out = g_RES @ Wt + bt
// ---------------------------------------------------------------------------
__global__ __launch_bounds__(256) void outproj_kernel(
    const float* __restrict__ Wt, const float* __restrict__ bt,
    float* __restrict__ out)
{
    __shared__ __align__(16) float WT[CH * WST];
    __shared__ __align__(16) float rowbuf[8][8 * CH];
    __shared__ float bsh[CH];

    int tid = threadIdx.x, lane = tid & 31, wid = tid >> 5;

    for (int i = tid; i < CH * CH; i += 256) {
        int t = i >> 6, c = i & 63;
        WT[c * WST + t] = Wt[i];
    }
    if (tid < CH) bsh[tid] = bt[tid];
    __syncthreads();

    int r0 = blockIdx.x * 64 + wid * 8;
    float* rb = &rowbuf[wid][0];
#pragma unroll
    for (int j = 0; j < 8; j++) {
        ((float2*)(rb + j * CH))[lane] =
            ((const float2*)(g_RES + (size_t)(r0 + j) * CH))[lane];
    }
    __syncwarp();

    unsigned long long accA[8], accB[8];
#pragma unroll
    for (int j = 0; j < 8; j++) { accA[j] = 0ull; accB[j] = 0ull; }
    const float* wr0 = WT + lane * WST;
    const float* wr1 = WT + (lane + 32) * WST;

#pragma unroll
    for (int t4 = 0; t4 < CH; t4 += 4) {
        ulonglong2 wa = *reinterpret_cast<const ulonglong2*>(wr0 + t4);
        ulonglong2 wb = *reinterpret_cast<const ulonglong2*>(wr1 + t4);
#pragma unroll
        for (int j = 0; j < 8; j++) {
            ulonglong2 hp = *reinterpret_cast<const ulonglong2*>(rb + j * CH + t4);
            accA[j] = fma2(hp.x, wa.x, accA[j]);
            accA[j] = fma2(hp.y, wa.y, accA[j]);
            accB[j] = fma2(hp.x, wb.x, accB[j]);
            accB[j] = fma2(hp.y, wb.y, accB[j]);
        }
    }
#pragma unroll
    for (int j = 0; j < 8; j++) {
        out[(size_t)(r0 + j) * CH + lane]      = hsum2(accA[j]) + bsh[lane];
        out[(size_t)(r0 + j) * CH + 32 + lane] = hsum2(accB[j]) + bsh[lane + 32];
    }
}

// ---------------------------------------------------------------------------
// kernel_launch   (attn is the 4th launch -> captured by ncu -s 5 -c 1)
// ---------------------------------------------------------------------------
extern "C" void kernel_launch(void* const* d_in, const int* in_sizes, int n_in,
                              void* d_out, int out_size)
{
    const float* q      = (const float*)d_in[0];
    const float* k      = (const float*)d_in[1];
    const float* value  = (const float*)d_in[2];
    const float* q_pos  = (const float*)d_in[3];
    const float* k_pos  = (const float*)d_in[4];
    const unsigned char* mask = (const unsigned char*)d_in[5];
    const int*   knn    = (const int*)d_in[6];
    const float* Wqk    = (const float*)d_in[8];
    const float* Wv     = (const float*)d_in[10];
    const float* bv     = (const float*)d_in[11];
    const float* Wg1    = (const float*)d_in[12];
    const float* bg1    = (const float*)d_in[13];
    const float* Wg2    = (const float*)d_in[14];
    const float* Wt     = (const float*)d_in[16];
    const float* bt     = (const float*)d_in[17];
    float* out = (float*)d_out;

    setup_kernel<<<49, 256>>>(Wqk, Wg1, Wg2, Wv, mask);
    project_kernel<<<(M_Q + N_K) / 64, 256>>>(q, q_pos, k, k_pos, bg1);
    dummy_kernel<<<1, 1>>>();
    attn_direct_kernel<<<M_Q / 4, 128>>>(value, mask, knn, bv);
    outproj_kernel<<<M_Q / 64, 256>>>(Wt, bt, out);
}

// round 14
// speedup vs baseline: 1.4037x; 1.3935x over previous
#include <cuda_runtime.h>
#include <cuda_bf16.h>
#include <cstdint>

// Problem constants
#define M_Q 65536
#define N_K 65536
#define KNB 16
#define CH  64
#define WST 68

// ---------------------------------------------------------------------------
// Device-global scratch
// ---------------------------------------------------------------------------
__device__ float g_A  [CH * CH];
__device__ float g_QG [M_Q * CH];
__device__ float g_KG [N_K * CH];
__device__ float g_RES[M_Q * CH];
__device__ int   g_mask_mode;
// B fragments: [nb(8)][gemm(2)][lane(32)][16 words]
__device__ unsigned int g_BF[8 * 2 * 32 * 16];

#define SWZ128(x) ((x) ^ (((x) >> 3) & 0x70))

// ---------------------------------------------------------------------------
// fp32x2 helpers
// ---------------------------------------------------------------------------
__device__ __forceinline__ unsigned long long fma2(unsigned long long a,
                                                   unsigned long long b,
                                                   unsigned long long c) {
    unsigned long long d;
    asm("fma.rn.f32x2 %0, %1, %2, %3;" : "=l"(d) : "l"(a), "l"(b), "l"(c));
    return d;
}
__device__ __forceinline__ float hsum2(unsigned long long v) {
    float lo, hi;
    asm("mov.b64 {%0, %1}, %2;" : "=f"(lo), "=f"(hi) : "l"(v));
    return lo + hi;
}

// ---------------------------------------------------------------------------
// bf16 split helpers
// ---------------------------------------------------------------------------
__device__ __forceinline__ unsigned int pack_hi(float x0, float x1,
                                                float& r0, float& r1) {
    __nv_bfloat16 b0 = __float2bfloat16(x0), b1 = __float2bfloat16(x1);
    r0 = x0 - __bfloat162float(b0);
    r1 = x1 - __bfloat162float(b1);
    return ((unsigned int)__bfloat16_as_ushort(b1) << 16) |
           (unsigned int)__bfloat16_as_ushort(b0);
}
__device__ __forceinline__ unsigned int pack_lo(float r0, float r1) {
    return ((unsigned int)__bfloat16_as_ushort(__float2bfloat16(r1)) << 16) |
           (unsigned int)__bfloat16_as_ushort(__float2bfloat16(r0));
}

// ---------------------------------------------------------------------------
// mma.sync / ldmatrix wrappers
// ---------------------------------------------------------------------------
__device__ __forceinline__ uint32_t smem_u32(const void* p) {
    uint32_t a;
    asm("{ .reg .u64 t; cvta.to.shared.u64 t, %1; cvt.u32.u64 %0, t; }"
        : "=r"(a) : "l"(p));
    return a;
}
__device__ __forceinline__ void ldsm_x4(uint32_t& a0, uint32_t& a1,
                                        uint32_t& a2, uint32_t& a3, uint32_t addr) {
    asm volatile("ldmatrix.sync.aligned.m8n8.x4.shared.b16 {%0,%1,%2,%3}, [%4];"
                 : "=r"(a0), "=r"(a1), "=r"(a2), "=r"(a3) : "r"(addr));
}
__device__ __forceinline__ void mma16816(float& c0, float& c1, float& c2, float& c3,
                                         uint32_t a0, uint32_t a1, uint32_t a2,
                                         uint32_t a3, uint32_t b0, uint32_t b1) {
    asm volatile(
        "mma.sync.aligned.m16n8k16.row.col.f32.bf16.bf16.f32 "
        "{%0,%1,%2,%3}, {%4,%5,%6,%7}, {%8,%9}, {%0,%1,%2,%3};"
        : "+f"(c0), "+f"(c1), "+f"(c2), "+f"(c3)
        : "r"(a0), "r"(a1), "r"(a2), "r"(a3), "r"(b0), "r"(b1));
}

// ---------------------------------------------------------------------------
// Kernel 1 (fused setup): blocks 0-15 A = Wqk@Wg1; 16-47 B fragments;
// block 48 mask dtype detection.
// ---------------------------------------------------------------------------
__global__ void setup_kernel(const float* __restrict__ Wqk,
                             const float* __restrict__ Wg1,
                             const float* __restrict__ Wg2,
                             const float* __restrict__ Wv,
                             const unsigned char* __restrict__ mask) {
    int b = blockIdx.x;
    if (b < 16) {
        int t = b * 256 + threadIdx.x;
        int r = t >> 6, c = t & 63;
        float s = 0.f;
#pragma unroll
        for (int u = 0; u < CH; u++) s += Wqk[r * CH + u] * Wg1[u * CH + c];
        g_A[t] = s;
    } else if (b < 48) {
        int idx = (b - 16) * 256 + threadIdx.x;
        int nb   = idx >> 10;
        int rem  = idx & 1023;
        int gm   = rem >> 9;
        int rem2 = rem & 511;
        int lane = rem2 >> 4;
        int w    = rem2 & 15;
        int split = w >> 3, kb = (w >> 1) & 3, r = w & 1;
        int t2 = lane & 3, gg = lane >> 2;
        int k0 = kb * 16 + 2 * t2 + (r ? 8 : 0);
        int n  = nb * 8 + gg;
        const float* W = gm ? Wv : Wg2;
        float w0 = W[k0 * CH + n];
        float w1 = W[(k0 + 1) * CH + n];
        unsigned int word;
        if (split == 0) { float r0, r1; word = pack_hi(w0, w1, r0, r1); }
        else {
            __nv_bfloat16 b0 = __float2bfloat16(w0), b1 = __float2bfloat16(w1);
            word = pack_lo(w0 - __bfloat162float(b0), w1 - __bfloat162float(b1));
        }
        g_BF[idx] = word;
    } else {
        __shared__ int sA, sB;
        int tid = threadIdx.x;
        if (tid == 0) { sA = 0; sB = 0; }
        __syncthreads();
        const uint4* p = (const uint4*)mask;
        int nvec = (M_Q * KNB) / 16;
        int fA = 0, fB = 0;
        for (int i = tid; i < nvec; i += blockDim.x) {
            uint4 v = p[i];
            unsigned w[4] = {v.x, v.y, v.z, v.w};
#pragma unroll
            for (int j = 0; j < 4; j++) {
                if ((w[j] >> 24) == 0x3fu) fA = 1;
                if (w[j] & 0x00ffff00u)    fB = 1;
                if ((w[j] >> 24) && ((w[j] >> 24) != 0x3fu)) fB = 1;
            }
        }
        if (fA) atomicOr(&sA, 1);
        if (fB) atomicOr(&sB, 1);
        __syncthreads();
        if (tid == 0) g_mask_mode = sA ? 2 : (sB ? 0 : 1);
    }
}

// ---------------------------------------------------------------------------
// Dummy no-op kernel (positions attn as the profiled 4th launch)
// ---------------------------------------------------------------------------
__global__ void dummy_kernel() {}

// ---------------------------------------------------------------------------
// Kernel 2: merged projection (fma2 path, unchanged)
// ---------------------------------------------------------------------------
__global__ __launch_bounds__(256) void project_kernel(
    const float* __restrict__ q, const float* __restrict__ q_pos,
    const float* __restrict__ k, const float* __restrict__ k_pos,
    const float* __restrict__ bg1)
{
    __shared__ __align__(16) float AT[CH * WST];
    __shared__ __align__(16) float rowbuf[8][8 * CH];
    __shared__ float bsh[CH];

    int tid = threadIdx.x, lane = tid & 31, wid = tid >> 5;

    for (int i = tid; i < CH * CH; i += 256) {
        int t = i >> 6, c = i & 63;
        AT[c * WST + t] = g_A[i];
    }
    if (tid < CH) bsh[tid] = bg1[tid];
    __syncthreads();

    int row0 = blockIdx.x * 64 + wid * 8;
    bool is_q = row0 < M_Q;
    const float* src = is_q ? q : k;
    const float* pos = is_q ? q_pos : k_pos;
    float* dst       = is_q ? g_QG : g_KG;
    int r0 = is_q ? row0 : row0 - M_Q;

    float* rb = &rowbuf[wid][0];
#pragma unroll
    for (int j = 0; j < 8; j++) {
        const float2* s2 = (const float2*)(src + (size_t)(r0 + j) * CH);
        const float2* p2 = (const float2*)(pos + (size_t)(r0 + j) * CH);
        float2 a = s2[lane], b = p2[lane];
        ((float2*)(rb + j * CH))[lane] = make_float2(a.x + b.x, a.y + b.y);
    }
    __syncwarp();

    unsigned long long accA[8], accB[8];
#pragma unroll
    for (int j = 0; j < 8; j++) { accA[j] = 0ull; accB[j] = 0ull; }
    const float* wr0 = AT + lane * WST;
    const float* wr1 = AT + (lane + 32) * WST;

#pragma unroll
    for (int t4 = 0; t4 < CH; t4 += 4) {
        ulonglong2 wa = *reinterpret_cast<const ulonglong2*>(wr0 + t4);
        ulonglong2 wb = *reinterpret_cast<const ulonglong2*>(wr1 + t4);
#pragma unroll
        for (int j = 0; j < 8; j++) {
            ulonglong2 hp = *reinterpret_cast<const ulonglong2*>(rb + j * CH + t4);
            accA[j] = fma2(hp.x, wa.x, accA[j]);
            accA[j] = fma2(hp.y, wa.y, accA[j]);
            accB[j] = fma2(hp.x, wb.x, accB[j]);
            accB[j] = fma2(hp.y, wb.y, accB[j]);
        }
    }
    float b0 = is_q ? bsh[lane] : 0.f;
    float b1 = is_q ? bsh[lane + 32] : 0.f;
#pragma unroll
    for (int j = 0; j < 8; j++) {
        dst[(size_t)(r0 + j) * CH + lane]      = hsum2(accA[j]) + b0;
        dst[(size_t)(r0 + j) * CH + 32 + lane] = hsum2(accB[j]) + b1;
    }
}

// ---------------------------------------------------------------------------
// Kernel 3: HMMA attention. Warp = 4 m-blocks x 2 n-blocks.
//   B fragments for BOTH gemms loaded ONCE (64 regs); accumulators only
//   16 regs live -> no spills. smem tiles + ldsm (redundancy 4x, cheap).
// smem: h_hi 16K | h_lo 16K | v_hi 16K | v_lo 16K | mask 512 = 66048 B
// ---------------------------------------------------------------------------
#define SM_HH 0
#define SM_HL 16384
#define SM_VH 32768
#define SM_VL 49152
#define SM_MK 65536
#define ATT_SMEM 66048

__global__ __launch_bounds__(256, 2) void attn_mma_kernel(
    const float* __restrict__ value, const unsigned char* __restrict__ mask,
    const int* __restrict__ knn, const float* __restrict__ bv)
{
    extern __shared__ __align__(1024) char smc[];
    int* smask = (int*)(smc + SM_MK);

    int tid = threadIdx.x, lane = tid & 31, wid = tid >> 5;
    int m0 = blockIdx.x * 8;
    int t = lane & 3, gg = lane >> 2;

    uint32_t sb_hh = smem_u32(smc + SM_HH);
    uint32_t sb_hl = smem_u32(smc + SM_HL);
    uint32_t sb_vh = smem_u32(smc + SM_VH);
    uint32_t sb_vl = smem_u32(smc + SM_VL);

    // ---- mask preload ----
    if (tid < 128) {
        int qloc = tid >> 4, e = tid & 15;
        size_t ix = (size_t)(m0 + qloc) * KNB + e;
        int mmode = g_mask_mode, mk;
        if (mmode == 0)      mk = mask[ix] != 0;
        else if (mmode == 1) mk = ((const int*)mask)[ix] != 0;
        else                 mk = ((const float*)mask)[ix] != 0.f;
        smask[tid] = mk;
    }

    // ---- build h AND value tiles upfront (warp w = query w) ----
    int mq = m0 + wid;
    int nbr = 0;
    if (lane < KNB) nbr = knn[(size_t)M_Q * KNB + (size_t)mq * KNB + lane];
    float2 qg = ((const float2*)(g_QG + (size_t)mq * CH))[lane];

#pragma unroll
    for (int e = 0; e < KNB; e++) {
        int n = __shfl_sync(0xffffffffu, nbr, e);
        float2 kg = ((const float2*)(g_KG + (size_t)n * CH))[lane];
        float x0 = fmaxf(qg.x - kg.x, 0.f), x1 = fmaxf(qg.y - kg.y, 0.f);
        unsigned off = SWZ128((unsigned)((wid * KNB + e) * 128 + lane * 4));
        float r0, r1;
        unsigned hiw = pack_hi(x0, x1, r0, r1);
        *(unsigned*)(smc + SM_HH + off) = hiw;
        *(unsigned*)(smc + SM_HL + off) = pack_lo(r0, r1);
    }
#pragma unroll
    for (int e = 0; e < KNB; e++) {
        float2 v2 = ((const float2*)(value + ((size_t)mq * KNB + e) * CH))[lane];
        unsigned off = SWZ128((unsigned)((wid * KNB + e) * 128 + lane * 4));
        float r0, r1;
        unsigned hiw = pack_hi(v2.x, v2.y, r0, r1);
        *(unsigned*)(smc + SM_VH + off) = hiw;
        *(unsigned*)(smc + SM_VL + off) = pack_lo(r0, r1);
    }
    __syncthreads();

    int mg = wid >> 2;       // m-blocks [4mg, 4mg+4)
    int ng = wid & 3;        // n-blocks {2ng, 2ng+1}

    unsigned lmrow = (unsigned)(lane & 15);
    unsigned lmcol = (unsigned)((lane >> 4) & 1) * 16;

    // ---- B fragments, both gemms, both splits, 2 n-blocks: loaded ONCE ----
    uint32_t B1H[2][8], B1L[2][8], B2H[2][8], B2L[2][8];
#pragma unroll
    for (int nb = 0; nb < 2; nb++) {
        {
            const uint4* bp = (const uint4*)g_BF +
                ((size_t)((ng * 2 + nb) * 2 + 0) * 32 + lane) * 4;
            uint4 u0 = bp[0], u1 = bp[1], u2 = bp[2], u3 = bp[3];
            B1H[nb][0]=u0.x; B1H[nb][1]=u0.y; B1H[nb][2]=u0.z; B1H[nb][3]=u0.w;
            B1H[nb][4]=u1.x; B1H[nb][5]=u1.y; B1H[nb][6]=u1.z; B1H[nb][7]=u1.w;
            B1L[nb][0]=u2.x; B1L[nb][1]=u2.y; B1L[nb][2]=u2.z; B1L[nb][3]=u2.w;
            B1L[nb][4]=u3.x; B1L[nb][5]=u3.y; B1L[nb][6]=u3.z; B1L[nb][7]=u3.w;
        }
        {
            const uint4* bp = (const uint4*)g_BF +
                ((size_t)((ng * 2 + nb) * 2 + 1) * 32 + lane) * 4;
            uint4 u0 = bp[0], u1 = bp[1], u2 = bp[2], u3 = bp[3];
            B2H[nb][0]=u0.x; B2H[nb][1]=u0.y; B2H[nb][2]=u0.z; B2H[nb][3]=u0.w;
            B2H[nb][4]=u1.x; B2H[nb][5]=u1.y; B2H[nb][6]=u1.z; B2H[nb][7]=u1.w;
            B2L[nb][0]=u2.x; B2L[nb][1]=u2.y; B2L[nb][2]=u2.z; B2L[nb][3]=u2.w;
            B2L[nb][4]=u3.x; B2L[nb][5]=u3.y; B2L[nb][6]=u3.z; B2L[nb][7]=u3.w;
        }
    }

    float2 bvv[2];
#pragma unroll
    for (int nb = 0; nb < 2; nb++)
        bvv[nb] = *(const float2*)(bv + (ng * 2 + nb) * 8 + 2 * t);

    // ---- per m-block: GEMM1 -> GEMM2 -> epilogue ----
#pragma unroll
    for (int mbi = 0; mbi < 4; mbi++) {
        int b = mg * 4 + mbi;
        unsigned rowoff = (unsigned)(b * 16 + lmrow) * 128 + lmcol;

        float c1[2][4];
#pragma unroll
        for (int nb = 0; nb < 2; nb++)
#pragma unroll
            for (int j = 0; j < 4; j++) c1[nb][j] = 0.f;
#pragma unroll
        for (int kb = 0; kb < 4; kb++) {
            unsigned off = SWZ128(rowoff + kb * 32);
            uint32_t a0, a1, a2, a3, l0, l1, l2, l3;
            ldsm_x4(a0, a1, a2, a3, sb_hh + off);
            ldsm_x4(l0, l1, l2, l3, sb_hl + off);
#pragma unroll
            for (int nb = 0; nb < 2; nb++)
                mma16816(c1[nb][0], c1[nb][1], c1[nb][2], c1[nb][3],
                         a0, a1, a2, a3, B1H[nb][kb*2], B1H[nb][kb*2+1]);
#pragma unroll
            for (int nb = 0; nb < 2; nb++)
                mma16816(c1[nb][0], c1[nb][1], c1[nb][2], c1[nb][3],
                         a0, a1, a2, a3, B1L[nb][kb*2], B1L[nb][kb*2+1]);
#pragma unroll
            for (int nb = 0; nb < 2; nb++)
                mma16816(c1[nb][0], c1[nb][1], c1[nb][2], c1[nb][3],
                         l0, l1, l2, l3, B1H[nb][kb*2], B1H[nb][kb*2+1]);
        }

        float c2[2][4];
#pragma unroll
        for (int nb = 0; nb < 2; nb++)
#pragma unroll
            for (int j = 0; j < 4; j++) c2[nb][j] = 0.f;
#pragma unroll
        for (int kb = 0; kb < 4; kb++) {
            unsigned off = SWZ128(rowoff + kb * 32);
            uint32_t a0, a1, a2, a3, l0, l1, l2, l3;
            ldsm_x4(a0, a1, a2, a3, sb_vh + off);
            ldsm_x4(l0, l1, l2, l3, sb_vl + off);
#pragma unroll
            for (int nb = 0; nb < 2; nb++)
                mma16816(c2[nb][0], c2[nb][1], c2[nb][2], c2[nb][3],
                         a0, a1, a2, a3, B2H[nb][kb*2], B2H[nb][kb*2+1]);
#pragma unroll
            for (int nb = 0; nb < 2; nb++)
                mma16816(c2[nb][0], c2[nb][1], c2[nb][2], c2[nb][3],
                         a0, a1, a2, a3, B2L[nb][kb*2], B2L[nb][kb*2+1]);
#pragma unroll
            for (int nb = 0; nb < 2; nb++)
                mma16816(c2[nb][0], c2[nb][1], c2[nb][2], c2[nb][3],
                         l0, l1, l2, l3, B2H[nb][kb*2], B2H[nb][kb*2+1]);
        }

        // ---- fused epilogue (no max-sub; masked p = 0) ----
        int mka = smask[b * 16 + gg];
        int mkb = smask[b * 16 + gg + 8];
#pragma unroll
        for (int nb = 0; nb < 2; nb++) {
            float p0 = mka ? 0.f : __expf(c1[nb][0]);
            float p1 = mka ? 0.f : __expf(c1[nb][1]);
            float p2 = mkb ? 0.f : __expf(c1[nb][2]);
            float p3 = mkb ? 0.f : __expf(c1[nb][3]);
            float s0 = p0 + p2, s1 = p1 + p3;
            float w0 = p0 * c2[nb][0] + p2 * c2[nb][2];
            float w1 = p1 * c2[nb][1] + p3 * c2[nb][3];
#pragma unroll
            for (int s = 4; s < 32; s <<= 1) {
                s0 += __shfl_xor_sync(0xffffffffu, s0, s);
                s1 += __shfl_xor_sync(0xffffffffu, s1, s);
                w0 += __shfl_xor_sync(0xffffffffu, w0, s);
                w1 += __shfl_xor_sync(0xffffffffu, w1, s);
            }
            if (lane < 4) {
                float2 o = make_float2(w0 / s0 + bvv[nb].x, w1 / s1 + bvv[nb].y);
                *(float2*)(g_RES + (size_t)(m0 + b) * CH + (ng * 2 + nb) * 8 + 2 * t) = o;
            }
        }
    }
}

// ---------------------------------------------------------------------------
// Kernel 4: out = g_RES @ Wt + bt
// ---------------------------------------------------------------------------
__global__ __launch_bounds__(256) void outproj_kernel(
    const float* __restrict__ Wt, const float* __restrict__ bt,
    float* __restrict__ out)
{
    __shared__ __align__(16) float WT[CH * WST];
    __shared__ __align__(16) float rowbuf[8][8 * CH];
    __shared__ float bsh[CH];

    int tid = threadIdx.x, lane = tid & 31, wid = tid >> 5;

    for (int i = tid; i < CH * CH; i += 256) {
        int t = i >> 6, c = i & 63;
        WT[c * WST + t] = Wt[i];
    }
    if (tid < CH) bsh[tid] = bt[tid];
    __syncthreads();

    int r0 = blockIdx.x * 64 + wid * 8;
    float* rb = &rowbuf[wid][0];
#pragma unroll
    for (int j = 0; j < 8; j++) {
        ((float2*)(rb + j * CH))[lane] =
            ((const float2*)(g_RES + (size_t)(r0 + j) * CH))[lane];
    }
    __syncwarp();

    unsigned long long accA[8], accB[8];
#pragma unroll
    for (int j = 0; j < 8; j++) { accA[j] = 0ull; accB[j] = 0ull; }
    const float* wr0 = WT + lane * WST;
    const float* wr1 = WT + (lane + 32) * WST;

#pragma unroll
    for (int t4 = 0; t4 < CH; t4 += 4) {
        ulonglong2 wa = *reinterpret_cast<const ulonglong2*>(wr0 + t4);
        ulonglong2 wb = *reinterpret_cast<const ulonglong2*>(wr1 + t4);
#pragma unroll
        for (int j = 0; j < 8; j++) {
            ulonglong2 hp = *reinterpret_cast<const ulonglong2*>(rb + j * CH + t4);
            accA[j] = fma2(hp.x, wa.x, accA[j]);
            accA[j] = fma2(hp.y, wa.y, accA[j]);
            accB[j] = fma2(hp.x, wb.x, accB[j]);
            accB[j] = fma2(hp.y, wb.y, accB[j]);
        }
    }
#pragma unroll
    for (int j = 0; j < 8; j++) {
        out[(size_t)(r0 + j) * CH + lane]      = hsum2(accA[j]) + bsh[lane];
        out[(size_t)(r0 + j) * CH + 32 + lane] = hsum2(accB[j]) + bsh[lane + 32];
    }
}

// ---------------------------------------------------------------------------
// kernel_launch   (attn is the 4th launch -> captured by ncu -s 5 -c 1)
// ---------------------------------------------------------------------------
extern "C" void kernel_launch(void* const* d_in, const int* in_sizes, int n_in,
                              void* d_out, int out_size)
{
    const float* q      = (const float*)d_in[0];
    const float* k      = (const float*)d_in[1];
    const float* value  = (const float*)d_in[2];
    const float* q_pos  = (const float*)d_in[3];
    const float* k_pos  = (const float*)d_in[4];
    const unsigned char* mask = (const unsigned char*)d_in[5];
    const int*   knn    = (const int*)d_in[6];
    const float* Wqk    = (const float*)d_in[8];
    const float* Wv     = (const float*)d_in[10];
    const float* bv     = (const float*)d_in[11];
    const float* Wg1    = (const float*)d_in[12];
    const float* bg1    = (const float*)d_in[13];
    const float* Wg2    = (const float*)d_in[14];
    const float* Wt     = (const float*)d_in[16];
    const float* bt     = (const float*)d_in[17];
    float* out = (float*)d_out;

    cudaFuncSetAttribute(attn_mma_kernel,
                         cudaFuncAttributeMaxDynamicSharedMemorySize, ATT_SMEM);

    setup_kernel<<<49, 256>>>(Wqk, Wg1, Wg2, Wv, mask);
    project_kernel<<<(M_Q + N_K) / 64, 256>>>(q, q_pos, k, k_pos, bg1);
    dummy_kernel<<<1, 1>>>();
    attn_mma_kernel<<<M_Q / 8, 256, ATT_SMEM>>>(value, mask, knn, bv);
    outproj_kernel<<<M_Q / 64, 256>>>(Wt, bt, out);
}

// round 17
// speedup vs baseline: 1.6578x; 1.1810x over previous
#include <cuda_runtime.h>
#include <cuda_bf16.h>
#include <cstdint>

// Problem constants
#define M_Q 65536
#define N_K 65536
#define KNB 16
#define CH  64
#define WST 68

// ---------------------------------------------------------------------------
// Device-global scratch
// ---------------------------------------------------------------------------
__device__ float g_A  [CH * CH];
__device__ float g_QG [M_Q * CH];
__device__ float g_KG [N_K * CH];
__device__ float g_RES[M_Q * CH];
__device__ int   g_flagA = 0;   // f32-signature flag (monotonic, replay-safe)
__device__ int   g_flagB = 0;   // nonzero-at-odd-offset flag
// B fragments: [nb(8)][gemm(2)][lane(32)][16 words]
__device__ unsigned int g_BF[8 * 2 * 32 * 16];

#define SWZ128(x) ((x) ^ (((x) >> 3) & 0x70))

// ---------------------------------------------------------------------------
// fp32x2 helpers
// ---------------------------------------------------------------------------
__device__ __forceinline__ unsigned long long fma2(unsigned long long a,
                                                   unsigned long long b,
                                                   unsigned long long c) {
    unsigned long long d;
    asm("fma.rn.f32x2 %0, %1, %2, %3;" : "=l"(d) : "l"(a), "l"(b), "l"(c));
    return d;
}
__device__ __forceinline__ float hsum2(unsigned long long v) {
    float lo, hi;
    asm("mov.b64 {%0, %1}, %2;" : "=f"(lo), "=f"(hi) : "l"(v));
    return lo + hi;
}

// ---------------------------------------------------------------------------
// bf16 split helpers
// ---------------------------------------------------------------------------
__device__ __forceinline__ unsigned int pack_hi(float x0, float x1,
                                                float& r0, float& r1) {
    __nv_bfloat16 b0 = __float2bfloat16(x0), b1 = __float2bfloat16(x1);
    r0 = x0 - __bfloat162float(b0);
    r1 = x1 - __bfloat162float(b1);
    return ((unsigned int)__bfloat16_as_ushort(b1) << 16) |
           (unsigned int)__bfloat16_as_ushort(b0);
}
__device__ __forceinline__ unsigned int pack_lo(float r0, float r1) {
    return ((unsigned int)__bfloat16_as_ushort(__float2bfloat16(r1)) << 16) |
           (unsigned int)__bfloat16_as_ushort(__float2bfloat16(r0));
}

// ---------------------------------------------------------------------------
// mma.sync / ldmatrix wrappers
// ---------------------------------------------------------------------------
__device__ __forceinline__ uint32_t smem_u32(const void* p) {
    uint32_t a;
    asm("{ .reg .u64 t; cvta.to.shared.u64 t, %1; cvt.u32.u64 %0, t; }"
        : "=r"(a) : "l"(p));
    return a;
}
__device__ __forceinline__ void ldsm_x4(uint32_t& a0, uint32_t& a1,
                                        uint32_t& a2, uint32_t& a3, uint32_t addr) {
    asm volatile("ldmatrix.sync.aligned.m8n8.x4.shared.b16 {%0,%1,%2,%3}, [%4];"
                 : "=r"(a0), "=r"(a1), "=r"(a2), "=r"(a3) : "r"(addr));
}
__device__ __forceinline__ void mma16816(float& c0, float& c1, float& c2, float& c3,
                                         uint32_t a0, uint32_t a1, uint32_t a2,
                                         uint32_t a3, uint32_t b0, uint32_t b1) {
    asm volatile(
        "mma.sync.aligned.m16n8k16.row.col.f32.bf16.bf16.f32 "
        "{%0,%1,%2,%3}, {%4,%5,%6,%7}, {%8,%9}, {%0,%1,%2,%3};"
        : "+f"(c0), "+f"(c1), "+f"(c2), "+f"(c3)
        : "r"(a0), "r"(a1), "r"(a2), "r"(a3), "r"(b0), "r"(b1));
}

// ---------------------------------------------------------------------------
// Kernel 1 (fused setup): blocks 0-15 A = Wqk@Wg1; 16-47 B fragments.
// ---------------------------------------------------------------------------
__global__ void setup_kernel(const float* __restrict__ Wqk,
                             const float* __restrict__ Wg1,
                             const float* __restrict__ Wg2,
                             const float* __restrict__ Wv) {
    int b = blockIdx.x;
    if (b < 16) {
        int t = b * 256 + threadIdx.x;
        int r = t >> 6, c = t & 63;
        float s = 0.f;
#pragma unroll
        for (int u = 0; u < CH; u++) s += Wqk[r * CH + u] * Wg1[u * CH + c];
        g_A[t] = s;
    } else {
        int idx = (b - 16) * 256 + threadIdx.x;
        int nb   = idx >> 10;
        int rem  = idx & 1023;
        int gm   = rem >> 9;
        int rem2 = rem & 511;
        int lane = rem2 >> 4;
        int w    = rem2 & 15;
        int split = w >> 3, kb = (w >> 1) & 3, r = w & 1;
        int t2 = lane & 3, gg = lane >> 2;
        int k0 = kb * 16 + 2 * t2 + (r ? 8 : 0);
        int n  = nb * 8 + gg;
        const float* W = gm ? Wv : Wg2;
        float w0 = W[k0 * CH + n];
        float w1 = W[(k0 + 1) * CH + n];
        unsigned int word;
        if (split == 0) { float r0, r1; word = pack_hi(w0, w1, r0, r1); }
        else {
            __nv_bfloat16 b0 = __float2bfloat16(w0), b1 = __float2bfloat16(w1);
            word = pack_lo(w0 - __bfloat162float(b0), w1 - __bfloat162float(b1));
        }
        g_BF[idx] = word;
    }
}

// ---------------------------------------------------------------------------
// Kernel 1b: parallel mask dtype detection (grid-stride, monotonic flags)
// ---------------------------------------------------------------------------
__global__ void mask_detect_kernel(const unsigned char* __restrict__ mask) {
    __shared__ int sA, sB;
    int tid = threadIdx.x;
    if (tid == 0) { sA = 0; sB = 0; }
    __syncthreads();
    const uint4* p = (const uint4*)mask;
    int nvec = (M_Q * KNB) / 16;
    int fA = 0, fB = 0;
    for (int i = blockIdx.x * blockDim.x + tid; i < nvec;
         i += gridDim.x * blockDim.x) {
        uint4 v = p[i];
        unsigned w[4] = {v.x, v.y, v.z, v.w};
#pragma unroll
        for (int j = 0; j < 4; j++) {
            if ((w[j] >> 24) == 0x3fu) fA = 1;
            if (w[j] & 0x00ffff00u)    fB = 1;
            if ((w[j] >> 24) && ((w[j] >> 24) != 0x3fu)) fB = 1;
        }
    }
    if (fA) atomicOr(&sA, 1);
    if (fB) atomicOr(&sB, 1);
    __syncthreads();
    if (tid == 0) {
        if (sA) atomicOr(&g_flagA, 1);
        if (sB) atomicOr(&g_flagB, 1);
    }
}

// ---------------------------------------------------------------------------
// Kernel 2: merged projection (fma2 path, unchanged)
// ---------------------------------------------------------------------------
__global__ __launch_bounds__(256) void project_kernel(
    const float* __restrict__ q, const float* __restrict__ q_pos,
    const float* __restrict__ k, const float* __restrict__ k_pos,
    const float* __restrict__ bg1)
{
    __shared__ __align__(16) float AT[CH * WST];
    __shared__ __align__(16) float rowbuf[8][8 * CH];
    __shared__ float bsh[CH];

    int tid = threadIdx.x, lane = tid & 31, wid = tid >> 5;

    for (int i = tid; i < CH * CH; i += 256) {
        int t = i >> 6, c = i & 63;
        AT[c * WST + t] = g_A[i];
    }
    if (tid < CH) bsh[tid] = bg1[tid];
    __syncthreads();

    int row0 = blockIdx.x * 64 + wid * 8;
    bool is_q = row0 < M_Q;
    const float* src = is_q ? q : k;
    const float* pos = is_q ? q_pos : k_pos;
    float* dst       = is_q ? g_QG : g_KG;
    int r0 = is_q ? row0 : row0 - M_Q;

    float* rb = &rowbuf[wid][0];
#pragma unroll
    for (int j = 0; j < 8; j++) {
        const float2* s2 = (const float2*)(src + (size_t)(r0 + j) * CH);
        const float2* p2 = (const float2*)(pos + (size_t)(r0 + j) * CH);
        float2 a = s2[lane], b = p2[lane];
        ((float2*)(rb + j * CH))[lane] = make_float2(a.x + b.x, a.y + b.y);
    }
    __syncwarp();

    unsigned long long accA[8], accB[8];
#pragma unroll
    for (int j = 0; j < 8; j++) { accA[j] = 0ull; accB[j] = 0ull; }
    const float* wr0 = AT + lane * WST;
    const float* wr1 = AT + (lane + 32) * WST;

#pragma unroll
    for (int t4 = 0; t4 < CH; t4 += 4) {
        ulonglong2 wa = *reinterpret_cast<const ulonglong2*>(wr0 + t4);
        ulonglong2 wb = *reinterpret_cast<const ulonglong2*>(wr1 + t4);
#pragma unroll
        for (int j = 0; j < 8; j++) {
            ulonglong2 hp = *reinterpret_cast<const ulonglong2*>(rb + j * CH + t4);
            accA[j] = fma2(hp.x, wa.x, accA[j]);
            accA[j] = fma2(hp.y, wa.y, accA[j]);
            accB[j] = fma2(hp.x, wb.x, accB[j]);
            accB[j] = fma2(hp.y, wb.y, accB[j]);
        }
    }
    float b0 = is_q ? bsh[lane] : 0.f;
    float b1 = is_q ? bsh[lane + 32] : 0.f;
#pragma unroll
    for (int j = 0; j < 8; j++) {
        dst[(size_t)(r0 + j) * CH + lane]      = hsum2(accA[j]) + b0;
        dst[(size_t)(r0 + j) * CH + 32 + lane] = hsum2(accB[j]) + b1;
    }
}

// ---------------------------------------------------------------------------
// Kernel 3: HMMA attention, phase-split B loading (32 B regs live at a time).
//   Warp = 4 m-blocks x 2 n-blocks. Phase 1: GEMM1 all m-blocks, logits in
//   regs (32). Phase 2: reload B with Wv frags, GEMM2 + fused epilogue.
// smem: h_hi 16K | h_lo 16K | v_hi 16K | v_lo 16K | mask 512 = 66048 B
// ---------------------------------------------------------------------------
#define SM_HH 0
#define SM_HL 16384
#define SM_VH 32768
#define SM_VL 49152
#define SM_MK 65536
#define ATT_SMEM 66048

__global__ __launch_bounds__(256, 2) void attn_mma_kernel(
    const float* __restrict__ value, const unsigned char* __restrict__ mask,
    const int* __restrict__ knn, const float* __restrict__ bv)
{
    extern __shared__ __align__(1024) char smc[];
    int* smask = (int*)(smc + SM_MK);

    int tid = threadIdx.x, lane = tid & 31, wid = tid >> 5;
    int m0 = blockIdx.x * 8;
    int t = lane & 3, gg = lane >> 2;

    uint32_t sb_hh = smem_u32(smc + SM_HH);
    uint32_t sb_hl = smem_u32(smc + SM_HL);
    uint32_t sb_vh = smem_u32(smc + SM_VH);
    uint32_t sb_vl = smem_u32(smc + SM_VL);

    // ---- mask preload (mode from flags) ----
    if (tid < 128) {
        int mmode = g_flagA ? 2 : (g_flagB ? 0 : 1);
        int qloc = tid >> 4, e = tid & 15;
        size_t ix = (size_t)(m0 + qloc) * KNB + e;
        int mk;
        if (mmode == 0)      mk = mask[ix] != 0;
        else if (mmode == 1) mk = ((const int*)mask)[ix] != 0;
        else                 mk = ((const float*)mask)[ix] != 0.f;
        smask[tid] = mk;
    }

    // ---- build h AND value tiles upfront (warp w = query w) ----
    int mq = m0 + wid;
    int nbr = 0;
    if (lane < KNB) nbr = knn[(size_t)M_Q * KNB + (size_t)mq * KNB + lane];
    float2 qg = ((const float2*)(g_QG + (size_t)mq * CH))[lane];

#pragma unroll
    for (int e = 0; e < KNB; e++) {
        int n = __shfl_sync(0xffffffffu, nbr, e);
        float2 kg = ((const float2*)(g_KG + (size_t)n * CH))[lane];
        float x0 = fmaxf(qg.x - kg.x, 0.f), x1 = fmaxf(qg.y - kg.y, 0.f);
        unsigned off = SWZ128((unsigned)((wid * KNB + e) * 128 + lane * 4));
        float r0, r1;
        unsigned hiw = pack_hi(x0, x1, r0, r1);
        *(unsigned*)(smc + SM_HH + off) = hiw;
        *(unsigned*)(smc + SM_HL + off) = pack_lo(r0, r1);
    }
#pragma unroll
    for (int e = 0; e < KNB; e++) {
        float2 v2 = ((const float2*)(value + ((size_t)mq * KNB + e) * CH))[lane];
        unsigned off = SWZ128((unsigned)((wid * KNB + e) * 128 + lane * 4));
        float r0, r1;
        unsigned hiw = pack_hi(v2.x, v2.y, r0, r1);
        *(unsigned*)(smc + SM_VH + off) = hiw;
        *(unsigned*)(smc + SM_VL + off) = pack_lo(r0, r1);
    }
    __syncthreads();

    int mg = wid >> 2;       // m-blocks [4mg, 4mg+4)
    int ng = wid & 3;        // n-blocks {2ng, 2ng+1}

    unsigned lmrow = (unsigned)(lane & 15);
    unsigned lmcol = (unsigned)((lane >> 4) & 1) * 16;

    uint32_t BH[2][8], BL[2][8];

    // ---- Phase 1: load Wg2 frags, GEMM1 for all 4 m-blocks ----
#pragma unroll
    for (int nb = 0; nb < 2; nb++) {
        const uint4* bp = (const uint4*)g_BF +
            ((size_t)((ng * 2 + nb) * 2 + 0) * 32 + lane) * 4;
        uint4 u0 = bp[0], u1 = bp[1], u2 = bp[2], u3 = bp[3];
        BH[nb][0]=u0.x; BH[nb][1]=u0.y; BH[nb][2]=u0.z; BH[nb][3]=u0.w;
        BH[nb][4]=u1.x; BH[nb][5]=u1.y; BH[nb][6]=u1.z; BH[nb][7]=u1.w;
        BL[nb][0]=u2.x; BL[nb][1]=u2.y; BL[nb][2]=u2.z; BL[nb][3]=u2.w;
        BL[nb][4]=u3.x; BL[nb][5]=u3.y; BL[nb][6]=u3.z; BL[nb][7]=u3.w;
    }

    float c1[4][2][4];
#pragma unroll
    for (int mbi = 0; mbi < 4; mbi++)
#pragma unroll
        for (int nb = 0; nb < 2; nb++)
#pragma unroll
            for (int j = 0; j < 4; j++) c1[mbi][nb][j] = 0.f;

#pragma unroll
    for (int mbi = 0; mbi < 4; mbi++) {
        int b = mg * 4 + mbi;
        unsigned rowoff = (unsigned)(b * 16 + lmrow) * 128 + lmcol;
#pragma unroll
        for (int kb = 0; kb < 4; kb++) {
            unsigned off = SWZ128(rowoff + kb * 32);
            uint32_t a0, a1, a2, a3, l0, l1, l2, l3;
            ldsm_x4(a0, a1, a2, a3, sb_hh + off);
            ldsm_x4(l0, l1, l2, l3, sb_hl + off);
#pragma unroll
            for (int nb = 0; nb < 2; nb++)
                mma16816(c1[mbi][nb][0], c1[mbi][nb][1], c1[mbi][nb][2], c1[mbi][nb][3],
                         a0, a1, a2, a3, BH[nb][kb*2], BH[nb][kb*2+1]);
#pragma unroll
            for (int nb = 0; nb < 2; nb++)
                mma16816(c1[mbi][nb][0], c1[mbi][nb][1], c1[mbi][nb][2], c1[mbi][nb][3],
                         a0, a1, a2, a3, BL[nb][kb*2], BL[nb][kb*2+1]);
#pragma unroll
            for (int nb = 0; nb < 2; nb++)
                mma16816(c1[mbi][nb][0], c1[mbi][nb][1], c1[mbi][nb][2], c1[mbi][nb][3],
                         l0, l1, l2, l3, BH[nb][kb*2], BH[nb][kb*2+1]);
        }
    }

    // ---- Phase 2: load Wv frags (overwrite), GEMM2 + epilogue ----
#pragma unroll
    for (int nb = 0; nb < 2; nb++) {
        const uint4* bp = (const uint4*)g_BF +
            ((size_t)((ng * 2 + nb) * 2 + 1) * 32 + lane) * 4;
        uint4 u0 = bp[0], u1 = bp[1], u2 = bp[2], u3 = bp[3];
        BH[nb][0]=u0.x; BH[nb][1]=u0.y; BH[nb][2]=u0.z; BH[nb][3]=u0.w;
        BH[nb][4]=u1.x; BH[nb][5]=u1.y; BH[nb][6]=u1.z; BH[nb][7]=u1.w;
        BL[nb][0]=u2.x; BL[nb][1]=u2.y; BL[nb][2]=u2.z; BL[nb][3]=u2.w;
        BL[nb][4]=u3.x; BL[nb][5]=u3.y; BL[nb][6]=u3.z; BL[nb][7]=u3.w;
    }

    float2 bvv[2];
#pragma unroll
    for (int nb = 0; nb < 2; nb++)
        bvv[nb] = *(const float2*)(bv + (ng * 2 + nb) * 8 + 2 * t);

#pragma unroll
    for (int mbi = 0; mbi < 4; mbi++) {
        int b = mg * 4 + mbi;
        unsigned rowoff = (unsigned)(b * 16 + lmrow) * 128 + lmcol;

        float c2[2][4];
#pragma unroll
        for (int nb = 0; nb < 2; nb++)
#pragma unroll
            for (int j = 0; j < 4; j++) c2[nb][j] = 0.f;
#pragma unroll
        for (int kb = 0; kb < 4; kb++) {
            unsigned off = SWZ128(rowoff + kb * 32);
            uint32_t a0, a1, a2, a3, l0, l1, l2, l3;
            ldsm_x4(a0, a1, a2, a3, sb_vh + off);
            ldsm_x4(l0, l1, l2, l3, sb_vl + off);
#pragma unroll
            for (int nb = 0; nb < 2; nb++)
                mma16816(c2[nb][0], c2[nb][1], c2[nb][2], c2[nb][3],
                         a0, a1, a2, a3, BH[nb][kb*2], BH[nb][kb*2+1]);
#pragma unroll
            for (int nb = 0; nb < 2; nb++)
                mma16816(c2[nb][0], c2[nb][1], c2[nb][2], c2[nb][3],
                         a0, a1, a2, a3, BL[nb][kb*2], BL[nb][kb*2+1]);
#pragma unroll
            for (int nb = 0; nb < 2; nb++)
                mma16816(c2[nb][0], c2[nb][1], c2[nb][2], c2[nb][3],
                         l0, l1, l2, l3, BH[nb][kb*2], BH[nb][kb*2+1]);
        }

        int mka = smask[b * 16 + gg];
        int mkb = smask[b * 16 + gg + 8];
#pragma unroll
        for (int nb = 0; nb < 2; nb++) {
            float p0 = mka ? 0.f : __expf(c1[mbi][nb][0]);
            float p1 = mka ? 0.f : __expf(c1[mbi][nb][1]);
            float p2 = mkb ? 0.f : __expf(c1[mbi][nb][2]);
            float p3 = mkb ? 0.f : __expf(c1[mbi][nb][3]);
            float s0 = p0 + p2, s1 = p1 + p3;
            float w0 = p0 * c2[nb][0] + p2 * c2[nb][2];
            float w1 = p1 * c2[nb][1] + p3 * c2[nb][3];
#pragma unroll
            for (int s = 4; s < 32; s <<= 1) {
                s0 += __shfl_xor_sync(0xffffffffu, s0, s);
                s1 += __shfl_xor_sync(0xffffffffu, s1, s);
                w0 += __shfl_xor_sync(0xffffffffu, w0, s);
                w1 += __shfl_xor_sync(0xffffffffu, w1, s);
            }
            if (lane < 4) {
                float2 o = make_float2(w0 / s0 + bvv[nb].x, w1 / s1 + bvv[nb].y);
                *(float2*)(g_RES + (size_t)(m0 + b) * CH + (ng * 2 + nb) * 8 + 2 * t) = o;
            }
        }
    }
}

// ---------------------------------------------------------------------------
// Kernel 4: out = g_RES @ Wt + bt
// ---------------------------------------------------------------------------
__global__ __launch_bounds__(256) void outproj_kernel(
    const float* __restrict__ Wt, const float* __restrict__ bt,
    float* __restrict__ out)
{
    __shared__ __align__(16) float WT[CH * WST];
    __shared__ __align__(16) float rowbuf[8][8 * CH];
    __shared__ float bsh[CH];

    int tid = threadIdx.x, lane = tid & 31, wid = tid >> 5;

    for (int i = tid; i < CH * CH; i += 256) {
        int t = i >> 6, c = i & 63;
        WT[c * WST + t] = Wt[i];
    }
    if (tid < CH) bsh[tid] = bt[tid];
    __syncthreads();

    int r0 = blockIdx.x * 64 + wid * 8;
    float* rb = &rowbuf[wid][0];
#pragma unroll
    for (int j = 0; j < 8; j++) {
        ((float2*)(rb + j * CH))[lane] =
            ((const float2*)(g_RES + (size_t)(r0 + j) * CH))[lane];
    }
    __syncwarp();

    unsigned long long accA[8], accB[8];
#pragma unroll
    for (int j = 0; j < 8; j++) { accA[j] = 0ull; accB[j] = 0ull; }
    const float* wr0 = WT + lane * WST;
    const float* wr1 = WT + (lane + 32) * WST;

#pragma unroll
    for (int t4 = 0; t4 < CH; t4 += 4) {
        ulonglong2 wa = *reinterpret_cast<const ulonglong2*>(wr0 + t4);
        ulonglong2 wb = *reinterpret_cast<const ulonglong2*>(wr1 + t4);
#pragma unroll
        for (int j = 0; j < 8; j++) {
            ulonglong2 hp = *reinterpret_cast<const ulonglong2*>(rb + j * CH + t4);
            accA[j] = fma2(hp.x, wa.x, accA[j]);
            accA[j] = fma2(hp.y, wa.y, accA[j]);
            accB[j] = fma2(hp.x, wb.x, accB[j]);
            accB[j] = fma2(hp.y, wb.y, accB[j]);
        }
    }
#pragma unroll
    for (int j = 0; j < 8; j++) {
        out[(size_t)(r0 + j) * CH + lane]      = hsum2(accA[j]) + bsh[lane];
        out[(size_t)(r0 + j) * CH + 32 + lane] = hsum2(accB[j]) + bsh[lane + 32];
    }
}

// ---------------------------------------------------------------------------
// kernel_launch   (attn is the 4th launch -> captured by ncu -s 5 -c 1)
// ---------------------------------------------------------------------------
extern "C" void kernel_launch(void* const* d_in, const int* in_sizes, int n_in,
                              void* d_out, int out_size)
{
    const float* q      = (const float*)d_in[0];
    const float* k      = (const float*)d_in[1];
    const float* value  = (const float*)d_in[2];
    const float* q_pos  = (const float*)d_in[3];
    const float* k_pos  = (const float*)d_in[4];
    const unsigned char* mask = (const unsigned char*)d_in[5];
    const int*   knn    = (const int*)d_in[6];
    const float* Wqk    = (const float*)d_in[8];
    const float* Wv     = (const float*)d_in[10];
    const float* bv     = (const float*)d_in[11];
    const float* Wg1    = (const float*)d_in[12];
    const float* bg1    = (const float*)d_in[13];
    const float* Wg2    = (const float*)d_in[14];
    const float* Wt     = (const float*)d_in[16];
    const float* bt     = (const float*)d_in[17];
    float* out = (float*)d_out;

    cudaFuncSetAttribute(attn_mma_kernel,
                         cudaFuncAttributeMaxDynamicSharedMemorySize, ATT_SMEM);

    setup_kernel<<<48, 256>>>(Wqk, Wg1, Wg2, Wv);
    mask_detect_kernel<<<128, 256>>>(mask);
    project_kernel<<<(M_Q + N_K) / 64, 256>>>(q, q_pos, k, k_pos, bg1);
    attn_mma_kernel<<<M_Q / 8, 256, ATT_SMEM>>>(value, mask, knn, bv);
    outproj_kernel<<<M_Q / 64, 256>>>(Wt, bt, out);
}